// round 15
// baseline (speedup 1.0000x reference)
#include <cuda_runtime.h>
#include <cuda_fp16.h>
#include <math.h>
#include <stdint.h>

#define S_LEN 2048
#define DIM 2048
#define NH 32
#define NKV 8
#define HD 64
#define QK_SCALE 0.125f
#define GK 2048
#define L2E 1.4426950408889634f

// ---- scratch (device globals; no allocation allowed) ----
__device__ __half g_qh[S_LEN * NH * HD];    // Q RoPE'd, scaled, fp16
__device__ __half g_kh[S_LEN * NKV * HD];   // K RoPE'd, fp16
__device__ __half g_vh[NKV * HD * S_LEN];   // V transposed [dim][seq], fp16
__device__ __half g_oh[S_LEN * NH * HD];    // attention out, fp16
__device__ __half g_xh[S_LEN * DIM];
__device__ __half g_wqh[NH * HD * DIM];
__device__ __half g_wkh[NKV * HD * DIM];
__device__ __half g_wvh[NKV * HD * DIM];
__device__ __half g_woh[DIM * NH * HD];

__device__ __forceinline__ void mma_f16(float* c, const uint32_t* a, const uint32_t* b) {
    asm volatile(
        "mma.sync.aligned.m16n8k16.row.col.f32.f16.f16.f32 "
        "{%0,%1,%2,%3}, {%4,%5,%6,%7}, {%8,%9}, {%0,%1,%2,%3};"
        : "+f"(c[0]), "+f"(c[1]), "+f"(c[2]), "+f"(c[3])
        : "r"(a[0]), "r"(a[1]), "r"(a[2]), "r"(a[3]), "r"(b[0]), "r"(b[1]));
}

__device__ __forceinline__ void ldsm4(uint32_t* r, uint32_t addr) {
    asm volatile("ldmatrix.sync.aligned.m8n8.x4.shared.b16 {%0,%1,%2,%3}, [%4];"
        : "=r"(r[0]), "=r"(r[1]), "=r"(r[2]), "=r"(r[3]) : "r"(addr));
}

__device__ __forceinline__ uint32_t pack_h2(float x, float y) {
    __half2 t = __floats2half2_rn(x, y);
    return *reinterpret_cast<uint32_t*>(&t);
}

__device__ __forceinline__ uint32_t h2ex2(uint32_t x) {
    uint32_t r;
    asm("ex2.approx.f16x2 %0, %1;" : "=r"(r) : "r"(x));
    return r;
}

__device__ __forceinline__ void cp16(void* smem_ptr, const void* gptr) {
    unsigned sa = (unsigned)__cvta_generic_to_shared(smem_ptr);
    asm volatile("cp.async.cg.shared.global [%0], [%1], 16;" :: "r"(sa), "l"(gptr));
}
#define CP_COMMIT() asm volatile("cp.async.commit_group;" ::: "memory")
#define CP_WAIT0()  asm volatile("cp.async.wait_group 0;" ::: "memory")
#define CP_WAIT1()  asm volatile("cp.async.wait_group 1;" ::: "memory")

// ============================================================================
// Pre-convert fp32 -> fp16 (single launch).
// ============================================================================
#define F4_X   1048576
#define F4_WQ  1048576
#define F4_WK  262144
#define F4_WV  262144
#define F4_WO  1048576

__global__ void conv5_kernel(const float4* __restrict__ x,
                             const float4* __restrict__ wq,
                             const float4* __restrict__ wk,
                             const float4* __restrict__ wv,
                             const float4* __restrict__ wo)
{
    int i = blockIdx.x * blockDim.x + threadIdx.x;
    const float4* s;
    __half* d;
    int off;
    if (i < F4_X)                       { s = x;  d = g_xh;  off = i; }
    else if (i < F4_X + F4_WQ)          { s = wq; d = g_wqh; off = i - F4_X; }
    else if (i < F4_X + F4_WQ + F4_WK)  { s = wk; d = g_wkh; off = i - F4_X - F4_WQ; }
    else if (i < F4_X + F4_WQ + F4_WK + F4_WV)
                                        { s = wv; d = g_wvh; off = i - F4_X - F4_WQ - F4_WK; }
    else                                { s = wo; d = g_woh; off = i - F4_X - F4_WQ - F4_WK - F4_WV; }
    float4 v = s[off];
    uint2 o;
    o.x = pack_h2(v.x, v.y);
    o.y = pack_h2(v.z, v.w);
    *(uint2*)(d + (size_t)off * 4) = o;
}

// ============================================================================
// FP16 GEMM NT core: BK=64, THREE-stage cp.async pipeline, ONE barrier/slab.
// Block 128x128x64, 8 warps, warp tile 32x64, ldmatrix fragments.
// Row stride 72 halves -> conflict-free LDSM phases.
// Buffer safety: at slab s the issue targets (s+2)%3 == (s-1)%3, whose
// compute finished before this iteration's barrier.
// EPI 0: fp32 C + bias. EPI 1: fp16 transposed (V). EPI 2/3: RoPE Q/K.
// ============================================================================
#define NSLAB 32                // K=2048 / 64
#define SMSH 72                 // halves per row
#define A_H (128 * SMSH)        // 9216 halves per matrix per stage
#define STG_H (2 * A_H)         // 18432 halves = 36864 B per stage

template <int EPI>
__device__ __forceinline__ void gemm_core_f16(
    const __half* __restrict__ A, const __half* __restrict__ B,
    const float* __restrict__ bias, float* __restrict__ C, __half* __restrict__ Ch,
    const float* __restrict__ rc,
    int N, int m0, int n0, __half* sm)
{
    const int tid = threadIdx.x;
    const int wid = tid >> 5;
    const int wm = wid & 3;
    const int wn = wid >> 2;
    const int l = tid & 31;
    const int l4 = l >> 2;
    const int lk2 = (l & 3) * 2;
    const int lrow = l & 15;            // ldmatrix lane row
    const int lcolh = (l >> 4) * 8;     // ldmatrix lane col (halves)

    const uint32_t smb = (uint32_t)__cvta_generic_to_shared(sm);

    const int frow = tid >> 3;          // 0..31 (x4 passes of 32 rows)
    const int fch = tid & 7;

    const __half* Ab = A + (size_t)(m0 + frow) * GK + fch * 8;
    const __half* Bb = B + (size_t)(n0 + frow) * GK + fch * 8;

    float acc[2][8][4];
    #pragma unroll
    for (int i = 0; i < 2; i++)
        #pragma unroll
        for (int j = 0; j < 8; j++)
            #pragma unroll
            for (int q = 0; q < 4; q++) acc[i][j][q] = 0.f;

    auto issue = [&](int slab, int slot) {
        __half* dst = sm + slot * STG_H;
        const int koff = slab * 64;
        #pragma unroll
        for (int i = 0; i < 4; i++) {
            const int row = frow + i * 32;
            cp16(dst + row * SMSH + fch * 8, Ab + (size_t)(i * 32) * GK + koff);
            cp16(dst + A_H + row * SMSH + fch * 8, Bb + (size_t)(i * 32) * GK + koff);
        }
        CP_COMMIT();
    };

    issue(0, 0);
    issue(1, 1);

    int bs = 0;   // s % 3
    for (int s = 0; s < NSLAB; s++) {
        if (s < NSLAB - 1) CP_WAIT1();
        else               CP_WAIT0();
        __syncthreads();

        // prefetch 2 slabs ahead into buffer (bs+2)%3 == (s-1)%3 (free)
        if (s + 2 < NSLAB) {
            int nslot = bs + 2;
            if (nslot >= 3) nslot -= 3;
            issue(s + 2, nslot);
        }

        const uint32_t sb = smb + bs * (STG_H * 2);
        const uint32_t abase = sb + 2 * ((wm * 32 + lrow) * SMSH + lcolh);
        const uint32_t bbase = sb + 2 * (A_H + (wn * 64 + lrow) * SMSH + lcolh);

        #pragma unroll
        for (int ks = 0; ks < 4; ks++) {
            uint32_t a[2][4], bt[4][4];
            #pragma unroll
            for (int tm = 0; tm < 2; tm++)
                ldsm4(a[tm], abase + 2 * (tm * 16 * SMSH + ks * 16));
            #pragma unroll
            for (int nt2 = 0; nt2 < 4; nt2++)
                ldsm4(bt[nt2], bbase + 2 * (nt2 * 16 * SMSH + ks * 16));
            #pragma unroll
            for (int tm = 0; tm < 2; tm++)
                #pragma unroll
                for (int nt = 0; nt < 8; nt++) {
                    uint32_t b2[2] = { bt[nt >> 1][nt & 1], bt[nt >> 1][(nt & 1) + 2] };
                    mma_f16(acc[tm][nt], a[tm], b2);
                }
        }

        if (++bs == 3) bs = 0;
    }

    if (EPI <= 1) {
        #pragma unroll
        for (int tm = 0; tm < 2; tm++) {
            const int row0 = m0 + wm * 32 + tm * 16 + l4;
            #pragma unroll
            for (int tn = 0; tn < 8; tn++) {
                const int col = n0 + wn * 64 + tn * 8 + lk2;
                const float b0 = bias[col];
                const float b1 = bias[col + 1];
                if (EPI == 0) {
                    float2 v0 = make_float2(acc[tm][tn][0] + b0, acc[tm][tn][1] + b1);
                    float2 v1 = make_float2(acc[tm][tn][2] + b0, acc[tm][tn][3] + b1);
                    *(float2*)(C + (size_t)row0 * N + col) = v0;
                    *(float2*)(C + (size_t)(row0 + 8) * N + col) = v1;
                } else {
                    Ch[(size_t)col * S_LEN + row0]           = __float2half_rn(acc[tm][tn][0] + b0);
                    Ch[(size_t)(col + 1) * S_LEN + row0]     = __float2half_rn(acc[tm][tn][1] + b1);
                    Ch[(size_t)col * S_LEN + row0 + 8]       = __float2half_rn(acc[tm][tn][2] + b0);
                    Ch[(size_t)(col + 1) * S_LEN + row0 + 8] = __float2half_rn(acc[tm][tn][3] + b1);
                }
            }
        }
    } else {
        // RoPE epilogue: pair (tn, tn+4) = dims (d, d+32) of one head.
        #pragma unroll
        for (int tm = 0; tm < 2; tm++) {
            const int r0 = m0 + wm * 32 + tm * 16 + l4;
            #pragma unroll
            for (int tn = 0; tn < 4; tn++) {
                const int col = n0 + wn * 64 + tn * 8 + lk2;
                const int d = tn * 8 + lk2;
                const float b1a = bias[col],      b1b = bias[col + 1];
                const float b2a = bias[col + 32], b2b = bias[col + 33];
                #pragma unroll
                for (int rr = 0; rr < 2; rr++) {
                    const int row = r0 + rr * 8;
                    const float2 cs = *(const float2*)(rc + row * HD + d);
                    const float2 sn = *(const float2*)(rc + row * HD + 32 + d);
                    const float x1a = acc[tm][tn][rr * 2 + 0] + b1a;
                    const float x1b = acc[tm][tn][rr * 2 + 1] + b1b;
                    const float x2a = acc[tm][tn + 4][rr * 2 + 0] + b2a;
                    const float x2b = acc[tm][tn + 4][rr * 2 + 1] + b2b;
                    float o1a = x1a * cs.x - x2a * sn.x;
                    float o1b = x1b * cs.y - x2b * sn.y;
                    float o2a = x1a * sn.x + x2a * cs.x;
                    float o2b = x1b * sn.y + x2b * cs.y;
                    if (EPI == 2) {
                        o1a *= QK_SCALE; o1b *= QK_SCALE;
                        o2a *= QK_SCALE; o2b *= QK_SCALE;
                    }
                    *(uint32_t*)(Ch + (size_t)row * N + col)      = pack_h2(o1a, o1b);
                    *(uint32_t*)(Ch + (size_t)row * N + col + 32) = pack_h2(o2a, o2b);
                }
            }
        }
    }
}

__global__ void __launch_bounds__(256, 2) gemm_qkv(
    const float* __restrict__ wq_b, const float* __restrict__ wk_b,
    const float* __restrict__ wv_b, const float* __restrict__ rc)
{
    extern __shared__ __half sm[];
    int id = blockIdx.x;
    if (id < 256) {
        gemm_core_f16<2>(g_xh, g_wqh, wq_b, nullptr, g_qh, rc, NH * HD, (id >> 4) * 128, (id & 15) * 128, sm);
    } else if (id < 320) {
        id -= 256;
        gemm_core_f16<3>(g_xh, g_wkh, wk_b, nullptr, g_kh, rc, NKV * HD, (id >> 2) * 128, (id & 3) * 128, sm);
    } else {
        id -= 320;
        gemm_core_f16<1>(g_xh, g_wvh, wv_b, nullptr, g_vh, nullptr, NKV * HD, (id >> 2) * 128, (id & 3) * 128, sm);
    }
}

__global__ void __launch_bounds__(256, 2) gemm_o(
    const float* __restrict__ wo_b, float* __restrict__ out)
{
    extern __shared__ __half sm[];
    const int id = blockIdx.x;
    gemm_core_f16<0>(g_oh, g_woh, wo_b, out, nullptr, nullptr, DIM, (id >> 4) * 128, (id & 15) * 128, sm);
}

// ============================================================================
// Flash attention, FP16 m16n8k16, P in registers, ldmatrix fragments,
// tensor-core row sums, THREE KV slots -> ONE barrier per tile, 2-deep
// prefetch. Stride 72 halves.
// ============================================================================
#define FSTRH 72
#define FTILE_H (64 * FSTRH)

__global__ void __launch_bounds__(128, 3) flash_tc(const float* __restrict__ sinks)
{
    extern __shared__ __half fsm[];
    const int h = blockIdx.y;
    const int kvh = h >> 2;
    const int qt = (int)gridDim.x - 1 - (int)blockIdx.x;   // heaviest first
    const int q0 = qt * 64;
    const int tid = threadIdx.x;
    const int w = tid >> 5;
    const int l = tid & 31;
    const int l4 = l >> 2;
    const int lk2 = (l & 3) * 2;
    const int lrow = l & 15;
    const int lcolh = (l >> 4) * 8;
    const uint32_t ONE2 = 0x3C003C00u;
    const uint32_t fmb = (uint32_t)__cvta_generic_to_shared(fsm);

    const int frow = tid >> 3;   // 0..15 per pass
    const int fch = tid & 7;

    // ---- stage Q tile into slot 0's K area ----
    #pragma unroll
    for (int i = 0; i < 4; i++) {
        const int row = frow + i * 16;
        cp16(fsm + row * FSTRH + fch * 8,
             g_qh + (size_t)(q0 + row) * (NH * HD) + h * HD + fch * 8);
    }
    CP_COMMIT();
    CP_WAIT0();
    __syncthreads();

    uint32_t qf[4][4];
    {
        const uint32_t qbase = fmb + 2 * ((w * 16 + lrow) * FSTRH + lcolh);
        #pragma unroll
        for (int kc = 0; kc < 4; kc++)
            ldsm4(qf[kc], qbase + 2 * (kc * 16));
    }
    __syncthreads();   // qf reads done before KV slot 0 overwrites

    auto issueKV = [&](int jt, int slot) {
        __half* Kb = fsm + slot * 2 * FTILE_H;
        __half* Vb = Kb + FTILE_H;
        const int j0 = jt * 64;
        #pragma unroll
        for (int i = 0; i < 4; i++) {
            const int row = frow + i * 16;
            cp16(Kb + row * FSTRH + fch * 8,
                 g_kh + (size_t)(j0 + row) * (NKV * HD) + kvh * HD + fch * 8);
            cp16(Vb + row * FSTRH + fch * 8,
                 g_vh + (size_t)(kvh * HD + row) * S_LEN + j0 + fch * 8);
        }
        CP_COMMIT();
    };

    float o[8][4];
    #pragma unroll
    for (int i = 0; i < 8; i++)
        #pragma unroll
        for (int j = 0; j < 4; j++) o[i][j] = 0.f;
    float os[4] = {0.f, 0.f, 0.f, 0.f};
    float m0 = -1e30f, m1 = -1e30f;

    issueKV(0, 0);
    if (qt >= 1) issueKV(1, 1);

    int bs = 0;   // jt % 3
    for (int jt = 0; jt <= qt; jt++) {
        if (jt < qt) CP_WAIT1();
        else         CP_WAIT0();
        __syncthreads();

        if (jt + 2 <= qt) {
            int nslot = bs + 2;
            if (nslot >= 3) nslot -= 3;
            issueKV(jt + 2, nslot);
        }

        const uint32_t kb = fmb + bs * (2 * FTILE_H * 2);
        const uint32_t vb = kb + FTILE_H * 2;
        const uint32_t kbase = kb + 2 * (lrow * FSTRH + lcolh);
        const uint32_t vbase = vb + 2 * (lrow * FSTRH + lcolh);

        // ---- S = Q K^T ----
        float c[8][4];
        #pragma unroll
        for (int i = 0; i < 8; i++)
            #pragma unroll
            for (int j = 0; j < 4; j++) c[i][j] = 0.f;
        #pragma unroll
        for (int kc = 0; kc < 4; kc++) {
            uint32_t bt[4][4];
            #pragma unroll
            for (int nt2 = 0; nt2 < 4; nt2++)
                ldsm4(bt[nt2], kbase + 2 * (nt2 * 16 * FSTRH + kc * 16));
            #pragma unroll
            for (int nt = 0; nt < 8; nt++) {
                uint32_t b2[2] = { bt[nt >> 1][nt & 1], bt[nt >> 1][(nt & 1) + 2] };
                mma_f16(c[nt], qf[kc], b2);
            }
        }

        // ---- causal mask (diagonal tile only) ----
        if (jt == qt) {
            const int row0 = w * 16 + l4, row1 = row0 + 8;
            #pragma unroll
            for (int nt = 0; nt < 8; nt++) {
                const int col = nt * 8 + lk2;
                if (col > row0)     c[nt][0] = -1e30f;
                if (col + 1 > row0) c[nt][1] = -1e30f;
                if (col > row1)     c[nt][2] = -1e30f;
                if (col + 1 > row1) c[nt][3] = -1e30f;
            }
        }

        // ---- online max ----
        float rmax0 = -1e30f, rmax1 = -1e30f;
        #pragma unroll
        for (int nt = 0; nt < 8; nt++) {
            rmax0 = fmaxf(rmax0, fmaxf(c[nt][0], c[nt][1]));
            rmax1 = fmaxf(rmax1, fmaxf(c[nt][2], c[nt][3]));
        }
        rmax0 = fmaxf(rmax0, __shfl_xor_sync(0xffffffffu, rmax0, 1));
        rmax0 = fmaxf(rmax0, __shfl_xor_sync(0xffffffffu, rmax0, 2));
        rmax1 = fmaxf(rmax1, __shfl_xor_sync(0xffffffffu, rmax1, 1));
        rmax1 = fmaxf(rmax1, __shfl_xor_sync(0xffffffffu, rmax1, 2));

        const float mn0 = fmaxf(m0, rmax0);
        const float mn1 = fmaxf(m1, rmax1);
        const float al0 = __expf(m0 - mn0);
        const float al1 = __expf(m1 - mn1);
        m0 = mn0; m1 = mn1;
        const float mb0 = mn0 * L2E;
        const float mb1 = mn1 * L2E;

        #pragma unroll
        for (int nt = 0; nt < 8; nt++) {
            o[nt][0] *= al0; o[nt][1] *= al0;
            o[nt][2] *= al1; o[nt][3] *= al1;
        }
        os[0] *= al0; os[1] *= al0;
        os[2] *= al1; os[3] *= al1;

        // ---- P as half2 fragments; O += P V; row sums += P * 1 ----
        #pragma unroll
        for (int kc = 0; kc < 4; kc++) {
            uint32_t a[4];
            a[0] = h2ex2(pack_h2(fmaf(c[2 * kc][0], L2E, -mb0),
                                 fmaf(c[2 * kc][1], L2E, -mb0)));
            a[1] = h2ex2(pack_h2(fmaf(c[2 * kc][2], L2E, -mb1),
                                 fmaf(c[2 * kc][3], L2E, -mb1)));
            a[2] = h2ex2(pack_h2(fmaf(c[2 * kc + 1][0], L2E, -mb0),
                                 fmaf(c[2 * kc + 1][1], L2E, -mb0)));
            a[3] = h2ex2(pack_h2(fmaf(c[2 * kc + 1][2], L2E, -mb1),
                                 fmaf(c[2 * kc + 1][3], L2E, -mb1)));
            uint32_t bt[4][4];
            #pragma unroll
            for (int nt2 = 0; nt2 < 4; nt2++)
                ldsm4(bt[nt2], vbase + 2 * (nt2 * 16 * FSTRH + kc * 16));
            #pragma unroll
            for (int nt = 0; nt < 8; nt++) {
                uint32_t b2[2] = { bt[nt >> 1][nt & 1], bt[nt >> 1][(nt & 1) + 2] };
                mma_f16(o[nt], a, b2);
            }
            uint32_t bo[2] = {ONE2, ONE2};
            mma_f16(os, a, bo);
        }

        if (++bs == 3) bs = 0;
    }

    // ---- epilogue: lse, sink sigmoid, normalize, store fp16 ----
    const float l0 = os[0];
    const float l1 = os[2];
    const float sk = sinks[h];
    const float lse0 = m0 + __logf(l0);
    const float lse1 = m1 + __logf(l1);
    const float w0 = (1.f / (1.f + __expf(sk - lse0))) / l0;
    const float w1 = (1.f / (1.f + __expf(sk - lse1))) / l1;
    const int row0 = q0 + w * 16 + l4;
    #pragma unroll
    for (int nt = 0; nt < 8; nt++) {
        const int col = h * HD + nt * 8 + lk2;
        *(uint32_t*)(g_oh + (size_t)row0 * (NH * HD) + col) =
            pack_h2(o[nt][0] * w0, o[nt][1] * w0);
        *(uint32_t*)(g_oh + (size_t)(row0 + 8) * (NH * HD) + col) =
            pack_h2(o[nt][2] * w1, o[nt][3] * w1);
    }
}

// ============================================================================
// launch
// ============================================================================
extern "C" void kernel_launch(void* const* d_in, const int* in_sizes, int n_in,
                              void* d_out, int out_size)
{
    const float* x     = (const float*)d_in[0];
    const float* rc    = (const float*)d_in[1];
    const float* wq_w  = (const float*)d_in[2];
    const float* wq_b  = (const float*)d_in[3];
    const float* wk_w  = (const float*)d_in[4];
    const float* wk_b  = (const float*)d_in[5];
    const float* wv_w  = (const float*)d_in[6];
    const float* wv_b  = (const float*)d_in[7];
    const float* wo_w  = (const float*)d_in[8];
    const float* wo_b  = (const float*)d_in[9];
    const float* sinks = (const float*)d_in[10];
    float* out = (float*)d_out;

    const int gemm_smem  = 3 * STG_H * 2;       // 110,592 B (3 stages)
    const int flash_smem = 6 * FTILE_H * 2;     // 55,296 B (3 KV slots)
    cudaFuncSetAttribute(gemm_qkv, cudaFuncAttributeMaxDynamicSharedMemorySize, gemm_smem);
    cudaFuncSetAttribute(gemm_o,   cudaFuncAttributeMaxDynamicSharedMemorySize, gemm_smem);
    cudaFuncSetAttribute(flash_tc, cudaFuncAttributeMaxDynamicSharedMemorySize, flash_smem);

    // 1. pre-convert x + weights to fp16
    conv5_kernel<<<(F4_X + F4_WQ + F4_WK + F4_WV + F4_WO) / 256, 256>>>(
        (const float4*)x, (const float4*)wq_w, (const float4*)wk_w,
        (const float4*)wv_w, (const float4*)wo_w);

    // 2. fused Q+K+V projections (RoPE fused into Q/K epilogues)
    gemm_qkv<<<384, 256, gemm_smem>>>(wq_b, wk_b, wv_b, rc);

    // 3. flash attention
    flash_tc<<<dim3(S_LEN / 64, NH), 128, flash_smem>>>(sinks);

    // 4. output projection
    gemm_o<<<256, 256, gemm_smem>>>(wo_b, out);
}